// round 2
// baseline (speedup 1.0000x reference)
#include <cuda_runtime.h>
#include <cstdint>

#define MAXN 100000
#define MAXE 1600000
#define F_INP 128
#define F_HID 64
#define F_OUT 40

// ---------------- device scratch (no allocations allowed) ----------------
__device__ int g_is64;
__device__ int g_indeg[MAXN];
__device__ int g_rowstart[MAXN + 1];
__device__ int g_cursor[MAXN];
__device__ float g_dinv[MAXN];
__device__ int g_bsum[128];
__device__ int g_bbase[128];
__device__ int g_csrc[MAXE];
__device__ __align__(256) float g_h[(size_t)MAXN * F_HID];   // h1' (scaled)
__device__ __align__(256) float g_o1[(size_t)MAXN * F_HID];  // relu layer-1 out
__device__ __align__(256) float g_h2[(size_t)MAXN * F_OUT];  // h2' (scaled)

// ---------------- f32x2 packed helpers (Blackwell) ----------------
static __device__ __forceinline__ unsigned long long pack2(float x, float y) {
    unsigned long long d;
    asm("mov.b64 %0, {%1, %2};" : "=l"(d) : "f"(x), "f"(y));
    return d;
}
static __device__ __forceinline__ void unpack2(unsigned long long a, float& x, float& y) {
    asm("mov.b64 {%0, %1}, %2;" : "=f"(x), "=f"(y) : "l"(a));
}
static __device__ __forceinline__ unsigned long long ffma2(
    unsigned long long a, unsigned long long b, unsigned long long c) {
    unsigned long long d;
    asm("fma.rn.f32x2 %0, %1, %2, %3;" : "=l"(d) : "l"(a), "l"(b), "l"(c));
    return d;
}

// ---------------- dtype detection: int64 vs int32 edge index ----------------
// int64 node ids < 2^31  =>  odd 32-bit words (hi halves) are all zero.
// int32 real data: odd words are random indices in [0,1e5) -> P(all 32 zero) ~ 0.
__global__ void detect_kernel(const unsigned int* __restrict__ w, int E) {
    int idx = 2 * threadIdx.x + 1;
    unsigned x = (idx < 2 * E) ? w[idx] : 0u;
    unsigned m = __ballot_sync(0xffffffffu, x != 0u);
    if (threadIdx.x == 0) g_is64 = (m == 0u) ? 1 : 0;
}

static __device__ __forceinline__ int edge_at(const void* ei, size_t idx, int is64) {
    return is64 ? (int)((const long long*)ei)[idx] : ((const int*)ei)[idx];
}

// ---------------- CSR build ----------------
__global__ void hist_kernel(const void* __restrict__ ei, int E) {
    int e = blockIdx.x * 256 + threadIdx.x;
    if (e >= E) return;
    int is64 = g_is64;
    int d = edge_at(ei, (size_t)E + e, is64);
    atomicAdd(&g_indeg[d], 1);
}

__global__ void scan_a_kernel(int N) {
    __shared__ int sh[1024];
    int i = blockIdx.x * 1024 + threadIdx.x;
    int x = (i < N) ? g_indeg[i] : 0;
    sh[threadIdx.x] = x;
    __syncthreads();
    for (int off = 512; off > 0; off >>= 1) {
        if (threadIdx.x < off) sh[threadIdx.x] += sh[threadIdx.x + off];
        __syncthreads();
    }
    if (threadIdx.x == 0) g_bsum[blockIdx.x] = sh[0];
}

__global__ void scan_b_kernel(int nb) {
    if (threadIdx.x == 0) {
        int run = 0;
        for (int i = 0; i < nb; i++) { g_bbase[i] = run; run += g_bsum[i]; }
    }
}

__global__ void scan_c_kernel(int N) {
    __shared__ int sh[1024];
    int i = blockIdx.x * 1024 + threadIdx.x;
    int x = (i < N) ? g_indeg[i] : 0;
    sh[threadIdx.x] = x;
    __syncthreads();
    for (int off = 1; off < 1024; off <<= 1) {
        int tv = (threadIdx.x >= off) ? sh[threadIdx.x - off] : 0;
        __syncthreads();
        sh[threadIdx.x] += tv;
        __syncthreads();
    }
    int incl = sh[threadIdx.x];
    int excl = incl - x;
    if (i < N) {
        int base = g_bbase[blockIdx.x];
        g_rowstart[i] = base + excl;
        g_cursor[i] = base + excl;
        g_dinv[i] = rsqrtf((float)(x + 1));  // deg includes self-loop
        if (i == N - 1) g_rowstart[N] = base + incl;
    }
}

__global__ void scatter_kernel(const void* __restrict__ ei, int E) {
    int e = blockIdx.x * 256 + threadIdx.x;
    if (e >= E) return;
    int is64 = g_is64;
    int s = edge_at(ei, (size_t)e, is64);
    int d = edge_at(ei, (size_t)E + e, is64);
    int pos = atomicAdd(&g_cursor[d], 1);
    g_csrc[pos] = s;
}

// ---------------- GEMM1: h' = (x @ W1) * dinv, one thread per node ----------------
__global__ __launch_bounds__(256) void gemm1_kernel(
    const float* __restrict__ x, const float* __restrict__ W1, int N) {
    __shared__ __align__(16) float sW[F_INP * F_HID];  // 32 KB
    for (int i = threadIdx.x; i < F_INP * F_HID; i += 256) sW[i] = W1[i];
    __syncthreads();
    int v = blockIdx.x * 256 + threadIdx.x;
    if (v >= N) return;

    unsigned long long acc[32];
#pragma unroll
    for (int j = 0; j < 32; j++) acc[j] = 0ull;

    const float4* xr = (const float4*)(x + (size_t)v * F_INP);
#pragma unroll 4
    for (int k4 = 0; k4 < F_INP / 4; k4++) {
        float4 xv = __ldg(&xr[k4]);
        float xs[4] = {xv.x, xv.y, xv.z, xv.w};
#pragma unroll
        for (int kk = 0; kk < 4; kk++) {
            unsigned long long xp = pack2(xs[kk], xs[kk]);
            const ulonglong2* wrow = (const ulonglong2*)(sW + (k4 * 4 + kk) * F_HID);
#pragma unroll
            for (int j = 0; j < 16; j++) {
                ulonglong2 wv = wrow[j];  // uniform address -> LDS broadcast
                acc[2 * j]     = ffma2(xp, wv.x, acc[2 * j]);
                acc[2 * j + 1] = ffma2(xp, wv.y, acc[2 * j + 1]);
            }
        }
    }
    float dv = g_dinv[v];
    float4* hout = (float4*)(g_h + (size_t)v * F_HID);
#pragma unroll
    for (int j = 0; j < 16; j++) {
        float a, b, c, d;
        unpack2(acc[2 * j], a, b);
        unpack2(acc[2 * j + 1], c, d);
        float4 o;
        o.x = a * dv; o.y = b * dv; o.z = c * dv; o.w = d * dv;
        hout[j] = o;
    }
}

// ---------------- Aggregate layer 1: 16 lanes/node, float4 each ----------------
__global__ __launch_bounds__(256) void agg1_kernel(const float* __restrict__ b1, int N) {
    int w = threadIdx.x >> 5, lane = threadIdx.x & 31;
    int t = lane & 15;
    int v = blockIdx.x * 16 + w * 2 + (lane >> 4);
    if (v >= N) return;
    const float4* h4 = (const float4*)g_h;
    float4 acc = h4[(size_t)v * 16 + t];  // self-loop term
    int i = g_rowstart[v], end = g_rowstart[v + 1];
    int s = (i < end) ? __ldg(&g_csrc[i]) : 0;
    while (i < end) {
        int snext = (i + 1 < end) ? __ldg(&g_csrc[i + 1]) : 0;  // pipeline idx load
        float4 m = h4[(size_t)s * 16 + t];
        acc.x += m.x; acc.y += m.y; acc.z += m.z; acc.w += m.w;
        s = snext;
        ++i;
    }
    float dv = g_dinv[v];
    float4 bb = ((const float4*)b1)[t];
    float4 o;
    o.x = fmaxf(fmaf(acc.x, dv, bb.x), 0.f);
    o.y = fmaxf(fmaf(acc.y, dv, bb.y), 0.f);
    o.z = fmaxf(fmaf(acc.z, dv, bb.z), 0.f);
    o.w = fmaxf(fmaf(acc.w, dv, bb.w), 0.f);
    ((float4*)g_o1)[(size_t)v * 16 + t] = o;
}

// ---------------- GEMM2: h2' = (o1 @ W2) * dinv ----------------
__global__ __launch_bounds__(256) void gemm2_kernel(const float* __restrict__ W2, int N) {
    __shared__ __align__(16) float sW[F_HID * F_OUT];  // 10.24 KB
    for (int i = threadIdx.x; i < F_HID * F_OUT; i += 256) sW[i] = W2[i];
    __syncthreads();
    int v = blockIdx.x * 256 + threadIdx.x;
    if (v >= N) return;

    unsigned long long acc[20];
#pragma unroll
    for (int j = 0; j < 20; j++) acc[j] = 0ull;

    const float4* xr = (const float4*)(g_o1 + (size_t)v * F_HID);
#pragma unroll 4
    for (int k4 = 0; k4 < F_HID / 4; k4++) {
        float4 xv = xr[k4];
        float xs[4] = {xv.x, xv.y, xv.z, xv.w};
#pragma unroll
        for (int kk = 0; kk < 4; kk++) {
            unsigned long long xp = pack2(xs[kk], xs[kk]);
            const ulonglong2* wrow = (const ulonglong2*)(sW + (k4 * 4 + kk) * F_OUT);
#pragma unroll
            for (int j = 0; j < 10; j++) {
                ulonglong2 wv = wrow[j];
                acc[2 * j]     = ffma2(xp, wv.x, acc[2 * j]);
                acc[2 * j + 1] = ffma2(xp, wv.y, acc[2 * j + 1]);
            }
        }
    }
    float dv = g_dinv[v];
    float4* hout = (float4*)(g_h2 + (size_t)v * F_OUT);
#pragma unroll
    for (int j = 0; j < 10; j++) {
        float a, b, c, d;
        unpack2(acc[2 * j], a, b);
        unpack2(acc[2 * j + 1], c, d);
        float4 o;
        o.x = a * dv; o.y = b * dv; o.z = c * dv; o.w = d * dv;
        hout[j] = o;
    }
}

// ---------------- Aggregate layer 2: 10 lanes/node (3 nodes/warp) ----------------
__global__ __launch_bounds__(256) void agg2_kernel(
    const float* __restrict__ b2, float* __restrict__ out, int N) {
    int w = threadIdx.x >> 5, lane = threadIdx.x & 31;
    int nw = lane / 10, t = lane - nw * 10;
    if (nw >= 3) return;  // lanes 30,31 idle
    int v = blockIdx.x * 24 + w * 3 + nw;
    if (v >= N) return;
    const float4* h4 = (const float4*)g_h2;
    float4 acc = h4[(size_t)v * 10 + t];  // self-loop term
    int i = g_rowstart[v], end = g_rowstart[v + 1];
    int s = (i < end) ? __ldg(&g_csrc[i]) : 0;
    while (i < end) {
        int snext = (i + 1 < end) ? __ldg(&g_csrc[i + 1]) : 0;
        float4 m = h4[(size_t)s * 10 + t];
        acc.x += m.x; acc.y += m.y; acc.z += m.z; acc.w += m.w;
        s = snext;
        ++i;
    }
    float dv = g_dinv[v];
    float4 bb = ((const float4*)b2)[t];
    float4 o;
    o.x = fmaf(acc.x, dv, bb.x);
    o.y = fmaf(acc.y, dv, bb.y);
    o.z = fmaf(acc.z, dv, bb.z);
    o.w = fmaf(acc.w, dv, bb.w);
    ((float4*)out)[(size_t)v * 10 + t] = o;
}

// ---------------- launch ----------------
extern "C" void kernel_launch(void* const* d_in, const int* in_sizes, int n_in,
                              void* d_out, int out_size) {
    const float* x  = (const float*)d_in[0];
    const void*  ei = d_in[1];
    const float* W1 = (const float*)d_in[2];
    const float* b1 = (const float*)d_in[3];
    const float* W2 = (const float*)d_in[4];
    const float* b2 = (const float*)d_in[5];

    int N = in_sizes[0] / F_INP;   // 100000
    int E = in_sizes[1] / 2;       // 1600000 (element count identical for i32/i64)

    int nbN  = (N + 255) / 256;
    int nbE  = (E + 255) / 256;
    int nbS  = (N + 1023) / 1024;

    // zero the in-degree histogram (capturable async memset, no allocation)
    void* indeg_ptr = nullptr;
    cudaGetSymbolAddress(&indeg_ptr, g_indeg);
    cudaMemsetAsync(indeg_ptr, 0, (size_t)N * sizeof(int));

    detect_kernel<<<1, 32>>>((const unsigned int*)ei, E);
    hist_kernel<<<nbE, 256>>>(ei, E);
    scan_a_kernel<<<nbS, 1024>>>(N);
    scan_b_kernel<<<1, 32>>>(nbS);
    scan_c_kernel<<<nbS, 1024>>>(N);
    scatter_kernel<<<nbE, 256>>>(ei, E);

    gemm1_kernel<<<nbN, 256>>>(x, W1, N);
    agg1_kernel<<<(N + 15) / 16, 256>>>(b1, N);
    gemm2_kernel<<<nbN, 256>>>(W2, N);
    agg2_kernel<<<(N + 23) / 24, 256>>>(b2, (float*)d_out, N);
}

// round 3
// speedup vs baseline: 1.1082x; 1.1082x over previous
#include <cuda_runtime.h>
#include <cuda_fp16.h>
#include <cstdint>

#define MAXN 100000
#define MAXE 1600000
#define F_INP 128
#define F_HID 64
#define F_OUT 40
#define H2_STRIDE 48  // 40 halves padded to 48 (96B rows, 3 aligned sectors)

// ---------------- device scratch (no allocations allowed) ----------------
__device__ int g_indeg[MAXN];
__device__ int g_rowstart[MAXN + 1];
__device__ int g_cursor[MAXN];
__device__ float g_dinv[MAXN];
__device__ int g_bsum[128];
__device__ int g_csrc[MAXE];
__device__ __align__(256) __half g_h[(size_t)MAXN * F_HID];       // h1' (scaled), fp16
__device__ __align__(256) __half g_o1[(size_t)MAXN * F_HID];      // relu layer-1 out, fp16
__device__ __align__(256) __half g_h2[(size_t)MAXN * H2_STRIDE];  // h2' (scaled), fp16 padded

// ---------------- f32x2 packed helpers (Blackwell) ----------------
static __device__ __forceinline__ unsigned long long pack2(float x, float y) {
    unsigned long long d;
    asm("mov.b64 %0, {%1, %2};" : "=l"(d) : "f"(x), "f"(y));
    return d;
}
static __device__ __forceinline__ void unpack2(unsigned long long a, float& x, float& y) {
    asm("mov.b64 {%0, %1}, %2;" : "=f"(x), "=f"(y) : "l"(a));
}
static __device__ __forceinline__ unsigned long long ffma2(
    unsigned long long a, unsigned long long b, unsigned long long c) {
    unsigned long long d;
    asm("fma.rn.f32x2 %0, %1, %2, %3;" : "=l"(d) : "l"(a), "l"(b), "l"(c));
    return d;
}

// ---------------- inline dtype detection (per-block, no extra kernel) ----------------
// int64 node ids < 2^31 => odd 32-bit words of ei are all zero.
static __device__ __forceinline__ int detect_is64(const unsigned* __restrict__ w, int E,
                                                  int* sflag) {
    if (threadIdx.x < 32) {
        int idx = 2 * threadIdx.x + 1;
        unsigned x = (idx < 2 * E) ? w[idx] : 0u;
        unsigned m = __ballot_sync(0xffffffffu, x != 0u);
        if (threadIdx.x == 0) *sflag = (m == 0u) ? 1 : 0;
    }
    __syncthreads();
    return *sflag;
}

static __device__ __forceinline__ int edge_at(const void* ei, size_t idx, int is64) {
    return is64 ? (int)((const long long*)ei)[idx] : ((const int*)ei)[idx];
}

// ---------------- CSR build ----------------
__global__ void hist_kernel(const void* __restrict__ ei, int E) {
    __shared__ int sflag;
    int is64 = detect_is64((const unsigned*)ei, E, &sflag);
    int e = blockIdx.x * 256 + threadIdx.x;
    if (e >= E) return;
    int d = edge_at(ei, (size_t)E + e, is64);
    atomicAdd(&g_indeg[d], 1);
}

__global__ void scan_a_kernel(int N) {
    __shared__ int sh[1024];
    int i = blockIdx.x * 1024 + threadIdx.x;
    int x = (i < N) ? g_indeg[i] : 0;
    sh[threadIdx.x] = x;
    __syncthreads();
    for (int off = 512; off > 0; off >>= 1) {
        if (threadIdx.x < off) sh[threadIdx.x] += sh[threadIdx.x + off];
        __syncthreads();
    }
    if (threadIdx.x == 0) g_bsum[blockIdx.x] = sh[0];
}

// block-local scan + per-block base computed in-kernel (warp reduce over <=128 sums)
__global__ void scan_c_kernel(int N) {
    __shared__ int sh[1024];
    __shared__ int sbase;
    if (threadIdx.x < 32) {
        int sum = 0;
        for (int i = threadIdx.x; i < (int)blockIdx.x; i += 32) sum += g_bsum[i];
        for (int o = 16; o > 0; o >>= 1) sum += __shfl_down_sync(0xffffffffu, sum, o);
        if (threadIdx.x == 0) sbase = sum;
    }
    int i = blockIdx.x * 1024 + threadIdx.x;
    int x = (i < N) ? g_indeg[i] : 0;
    sh[threadIdx.x] = x;
    __syncthreads();
    for (int off = 1; off < 1024; off <<= 1) {
        int tv = (threadIdx.x >= off) ? sh[threadIdx.x - off] : 0;
        __syncthreads();
        sh[threadIdx.x] += tv;
        __syncthreads();
    }
    int incl = sh[threadIdx.x];
    int excl = incl - x;
    if (i < N) {
        int base = sbase;
        g_rowstart[i] = base + excl;
        g_cursor[i] = base + excl;
        g_dinv[i] = rsqrtf((float)(x + 1));  // deg includes self-loop
        if (i == N - 1) g_rowstart[N] = base + incl;
    }
}

__global__ void scatter_kernel(const void* __restrict__ ei, int E) {
    __shared__ int sflag;
    int is64 = detect_is64((const unsigned*)ei, E, &sflag);
    int e = blockIdx.x * 256 + threadIdx.x;
    if (e >= E) return;
    int s = edge_at(ei, (size_t)e, is64);
    int d = edge_at(ei, (size_t)E + e, is64);
    int pos = atomicAdd(&g_cursor[d], 1);
    g_csrc[pos] = s;
}

// ---------------- GEMM1: h' = (x @ W1) * dinv  -> fp16 ----------------
__global__ __launch_bounds__(256) void gemm1_kernel(
    const float* __restrict__ x, const float* __restrict__ W1, int N) {
    __shared__ __align__(16) float sW[F_INP * F_HID];  // 32 KB
    for (int i = threadIdx.x; i < F_INP * F_HID; i += 256) sW[i] = W1[i];
    __syncthreads();
    int v = blockIdx.x * 256 + threadIdx.x;
    if (v >= N) return;

    unsigned long long acc[32];
#pragma unroll
    for (int j = 0; j < 32; j++) acc[j] = 0ull;

    const float4* xr = (const float4*)(x + (size_t)v * F_INP);
#pragma unroll 4
    for (int k4 = 0; k4 < F_INP / 4; k4++) {
        float4 xv = __ldg(&xr[k4]);
        float xs[4] = {xv.x, xv.y, xv.z, xv.w};
#pragma unroll
        for (int kk = 0; kk < 4; kk++) {
            unsigned long long xp = pack2(xs[kk], xs[kk]);
            const ulonglong2* wrow = (const ulonglong2*)(sW + (k4 * 4 + kk) * F_HID);
#pragma unroll
            for (int j = 0; j < 16; j++) {
                ulonglong2 wv = wrow[j];  // uniform address -> LDS broadcast
                acc[2 * j]     = ffma2(xp, wv.x, acc[2 * j]);
                acc[2 * j + 1] = ffma2(xp, wv.y, acc[2 * j + 1]);
            }
        }
    }
    float dv = g_dinv[v];
    uint4* hout = (uint4*)(g_h + (size_t)v * F_HID);
#pragma unroll
    for (int j = 0; j < 8; j++) {  // 8 channels per uint4
        float a, b;
        uint4 o;
        unpack2(acc[4 * j + 0], a, b);
        __half2 p0 = __floats2half2_rn(a * dv, b * dv);
        unpack2(acc[4 * j + 1], a, b);
        __half2 p1 = __floats2half2_rn(a * dv, b * dv);
        unpack2(acc[4 * j + 2], a, b);
        __half2 p2 = __floats2half2_rn(a * dv, b * dv);
        unpack2(acc[4 * j + 3], a, b);
        __half2 p3 = __floats2half2_rn(a * dv, b * dv);
        o.x = *reinterpret_cast<unsigned*>(&p0);
        o.y = *reinterpret_cast<unsigned*>(&p1);
        o.z = *reinterpret_cast<unsigned*>(&p2);
        o.w = *reinterpret_cast<unsigned*>(&p3);
        hout[j] = o;
    }
}

static __device__ __forceinline__ void add8(float* acc, uint4 m) {
    float2 f;
    f = __half22float2(*reinterpret_cast<__half2*>(&m.x)); acc[0] += f.x; acc[1] += f.y;
    f = __half22float2(*reinterpret_cast<__half2*>(&m.y)); acc[2] += f.x; acc[3] += f.y;
    f = __half22float2(*reinterpret_cast<__half2*>(&m.z)); acc[4] += f.x; acc[5] += f.y;
    f = __half22float2(*reinterpret_cast<__half2*>(&m.w)); acc[6] += f.x; acc[7] += f.y;
}

// ---------------- Aggregate layer 1: 8 lanes/node, 4 nodes/warp ----------------
__global__ __launch_bounds__(256) void agg1_kernel(const float* __restrict__ b1, int N) {
    int w = threadIdx.x >> 5, lane = threadIdx.x & 31;
    int t = lane & 7;
    int v = blockIdx.x * 32 + w * 4 + (lane >> 3);
    if (v >= N) return;
    const uint4* h4 = (const uint4*)g_h;
    float acc[8] = {0, 0, 0, 0, 0, 0, 0, 0};
    add8(acc, h4[(size_t)v * 8 + t]);  // self-loop term
    int i = g_rowstart[v], end = g_rowstart[v + 1];
    int s = (i < end) ? __ldg(&g_csrc[i]) : 0;
    while (i < end) {
        int snext = (i + 1 < end) ? __ldg(&g_csrc[i + 1]) : 0;  // pipeline idx load
        add8(acc, h4[(size_t)s * 8 + t]);
        s = snext;
        ++i;
    }
    float dv = g_dinv[v];
    float4 bA = ((const float4*)b1)[t * 2];
    float4 bB = ((const float4*)b1)[t * 2 + 1];
    float r0 = fmaxf(fmaf(acc[0], dv, bA.x), 0.f);
    float r1 = fmaxf(fmaf(acc[1], dv, bA.y), 0.f);
    float r2 = fmaxf(fmaf(acc[2], dv, bA.z), 0.f);
    float r3 = fmaxf(fmaf(acc[3], dv, bA.w), 0.f);
    float r4 = fmaxf(fmaf(acc[4], dv, bB.x), 0.f);
    float r5 = fmaxf(fmaf(acc[5], dv, bB.y), 0.f);
    float r6 = fmaxf(fmaf(acc[6], dv, bB.z), 0.f);
    float r7 = fmaxf(fmaf(acc[7], dv, bB.w), 0.f);
    __half2 p0 = __floats2half2_rn(r0, r1), p1 = __floats2half2_rn(r2, r3);
    __half2 p2 = __floats2half2_rn(r4, r5), p3 = __floats2half2_rn(r6, r7);
    uint4 o;
    o.x = *reinterpret_cast<unsigned*>(&p0);
    o.y = *reinterpret_cast<unsigned*>(&p1);
    o.z = *reinterpret_cast<unsigned*>(&p2);
    o.w = *reinterpret_cast<unsigned*>(&p3);
    ((uint4*)g_o1)[(size_t)v * 8 + t] = o;
}

// ---------------- GEMM2: h2' = (o1 @ W2) * dinv -> fp16 (stride 48) ----------------
__global__ __launch_bounds__(256) void gemm2_kernel(const float* __restrict__ W2, int N) {
    __shared__ __align__(16) float sW[F_HID * F_OUT];  // 10.24 KB
    for (int i = threadIdx.x; i < F_HID * F_OUT; i += 256) sW[i] = W2[i];
    __syncthreads();
    int v = blockIdx.x * 256 + threadIdx.x;
    if (v >= N) return;

    unsigned long long acc[20];
#pragma unroll
    for (int j = 0; j < 20; j++) acc[j] = 0ull;

    const uint4* xr = (const uint4*)(g_o1 + (size_t)v * F_HID);
#pragma unroll
    for (int k8 = 0; k8 < F_HID / 8; k8++) {
        uint4 xv = xr[k8];
        float xs[8];
        float2 f;
        f = __half22float2(*reinterpret_cast<__half2*>(&xv.x)); xs[0] = f.x; xs[1] = f.y;
        f = __half22float2(*reinterpret_cast<__half2*>(&xv.y)); xs[2] = f.x; xs[3] = f.y;
        f = __half22float2(*reinterpret_cast<__half2*>(&xv.z)); xs[4] = f.x; xs[5] = f.y;
        f = __half22float2(*reinterpret_cast<__half2*>(&xv.w)); xs[6] = f.x; xs[7] = f.y;
#pragma unroll
        for (int kk = 0; kk < 8; kk++) {
            unsigned long long xp = pack2(xs[kk], xs[kk]);
            const ulonglong2* wrow = (const ulonglong2*)(sW + (k8 * 8 + kk) * F_OUT);
#pragma unroll
            for (int j = 0; j < 10; j++) {
                ulonglong2 wv = wrow[j];
                acc[2 * j]     = ffma2(xp, wv.x, acc[2 * j]);
                acc[2 * j + 1] = ffma2(xp, wv.y, acc[2 * j + 1]);
            }
        }
    }
    float dv = g_dinv[v];
    uint4* hout = (uint4*)(g_h2 + (size_t)v * H2_STRIDE);
#pragma unroll
    for (int j = 0; j < 5; j++) {  // 5 uint4 = 40 halves
        float a, b;
        uint4 o;
        unpack2(acc[4 * j + 0], a, b);
        __half2 p0 = __floats2half2_rn(a * dv, b * dv);
        unpack2(acc[4 * j + 1], a, b);
        __half2 p1 = __floats2half2_rn(a * dv, b * dv);
        unpack2(acc[4 * j + 2], a, b);
        __half2 p2 = __floats2half2_rn(a * dv, b * dv);
        unpack2(acc[4 * j + 3], a, b);
        __half2 p3 = __floats2half2_rn(a * dv, b * dv);
        o.x = *reinterpret_cast<unsigned*>(&p0);
        o.y = *reinterpret_cast<unsigned*>(&p1);
        o.z = *reinterpret_cast<unsigned*>(&p2);
        o.w = *reinterpret_cast<unsigned*>(&p3);
        hout[j] = o;
    }
}

// ---------------- Aggregate layer 2: 5 lanes/node, 6 nodes/warp ----------------
__global__ __launch_bounds__(256) void agg2_kernel(
    const float* __restrict__ b2, float* __restrict__ out, int N) {
    int w = threadIdx.x >> 5, lane = threadIdx.x & 31;
    int nw = lane / 5, t = lane - nw * 5;
    if (nw >= 6) return;  // lanes 30,31 idle
    int v = blockIdx.x * 48 + w * 6 + nw;
    if (v >= N) return;
    const uint4* h4 = (const uint4*)g_h2;  // row = 6 uint4 (stride 48 halves)
    float acc[8] = {0, 0, 0, 0, 0, 0, 0, 0};
    add8(acc, h4[(size_t)v * 6 + t]);  // self-loop term
    int i = g_rowstart[v], end = g_rowstart[v + 1];
    int s = (i < end) ? __ldg(&g_csrc[i]) : 0;
    while (i < end) {
        int snext = (i + 1 < end) ? __ldg(&g_csrc[i + 1]) : 0;
        add8(acc, h4[(size_t)s * 6 + t]);
        s = snext;
        ++i;
    }
    float dv = g_dinv[v];
    float4 bA = ((const float4*)b2)[t * 2];
    float4 bB = ((const float4*)b2)[t * 2 + 1];
    float4 oA, oB;
    oA.x = fmaf(acc[0], dv, bA.x);
    oA.y = fmaf(acc[1], dv, bA.y);
    oA.z = fmaf(acc[2], dv, bA.z);
    oA.w = fmaf(acc[3], dv, bA.w);
    oB.x = fmaf(acc[4], dv, bB.x);
    oB.y = fmaf(acc[5], dv, bB.y);
    oB.z = fmaf(acc[6], dv, bB.z);
    oB.w = fmaf(acc[7], dv, bB.w);
    float4* orow = (float4*)(out + (size_t)v * F_OUT + t * 8);
    orow[0] = oA;
    orow[1] = oB;
}

// ---------------- launch ----------------
extern "C" void kernel_launch(void* const* d_in, const int* in_sizes, int n_in,
                              void* d_out, int out_size) {
    const float* x  = (const float*)d_in[0];
    const void*  ei = d_in[1];
    const float* W1 = (const float*)d_in[2];
    const float* b1 = (const float*)d_in[3];
    const float* W2 = (const float*)d_in[4];
    const float* b2 = (const float*)d_in[5];

    int N = in_sizes[0] / F_INP;   // 100000
    int E = in_sizes[1] / 2;       // 1600000 (element count identical for i32/i64)

    int nbN = (N + 255) / 256;
    int nbE = (E + 255) / 256;
    int nbS = (N + 1023) / 1024;

    // zero the in-degree histogram (capturable async memset, no allocation)
    void* indeg_ptr = nullptr;
    cudaGetSymbolAddress(&indeg_ptr, g_indeg);
    cudaMemsetAsync(indeg_ptr, 0, (size_t)N * sizeof(int));

    hist_kernel<<<nbE, 256>>>(ei, E);
    scan_a_kernel<<<nbS, 1024>>>(N);
    scan_c_kernel<<<nbS, 1024>>>(N);
    scatter_kernel<<<nbE, 256>>>(ei, E);

    gemm1_kernel<<<nbN, 256>>>(x, W1, N);
    agg1_kernel<<<(N + 31) / 32, 256>>>(b1, N);
    gemm2_kernel<<<nbN, 256>>>(W2, N);
    agg2_kernel<<<(N + 47) / 48, 256>>>(b2, (float*)d_out, N);
}